// round 14
// baseline (speedup 1.0000x reference)
#include <cuda_runtime.h>
#include <cuda_fp16.h>
#include <math.h>

#define B 4
#define M 2048
#define DMODEL 512
#define NHEAD 8
#define DHEAD 64
#define NTOK (B*M)          // 8192
#define BH (B*NHEAD)        // 32

// ---------------- scratch (device globals) ----------------
__device__ __half g_x[NTOK * DMODEL];     // h, fp16
__device__ __half g_wq[DMODEL * DMODEL];  // weights, fp16
__device__ __half g_wk[DMODEL * DMODEL];
__device__ __half g_wv[DMODEL * DMODEL];
__device__ __half g_wo[DMODEL * DMODEL];
__device__ __half g_q[BH * M * DHEAD];    // [b,h,m,dh], fp16, pre-scaled 1/8
__device__ __half g_k[BH * M * DHEAD];    // [b,h,m,dh] fp16
__device__ __half g_v[BH * DHEAD * M];    // [b,h,dh,m] TRANSPOSED, fp16
__device__ __half g_ao[NTOK * DMODEL];    // attention output [b,m,d], fp16
__device__ float  g_bias[M];              // log(exp(-d)+1e-12)
__device__ int    g_mask[NTOK];
__device__ unsigned g_mbits[NTOK / 32];   // packed mask bits

// ---------------- ptx helpers ----------------
__device__ __forceinline__ unsigned smem_u32(const void* p) {
    return (unsigned)__cvta_generic_to_shared(p);
}
__device__ __forceinline__ void cp16(unsigned d, const void* s) {
    asm volatile("cp.async.cg.shared.global [%0],[%1],16;\n" :: "r"(d), "l"(s) : "memory");
}
__device__ __forceinline__ void cp_commit() {
    asm volatile("cp.async.commit_group;\n" ::: "memory");
}
template<int N> __device__ __forceinline__ void cp_wait() {
    asm volatile("cp.async.wait_group %0;\n" :: "n"(N) : "memory");
}
// fp16 mma: D(f32) += A(f16 4reg) * B(f16 2reg), m16n8k16 row.col
__device__ __forceinline__ void mma16(float* c, const unsigned* a, const unsigned* b) {
    asm volatile(
        "mma.sync.aligned.m16n8k16.row.col.f32.f16.f16.f32 "
        "{%0,%1,%2,%3},{%4,%5,%6,%7},{%8,%9},{%0,%1,%2,%3};\n"
        : "+f"(c[0]), "+f"(c[1]), "+f"(c[2]), "+f"(c[3])
        : "r"(a[0]), "r"(a[1]), "r"(a[2]), "r"(a[3]), "r"(b[0]), "r"(b[1]));
}
__device__ __forceinline__ void ldsm4(unsigned& r0, unsigned& r1, unsigned& r2, unsigned& r3,
                                      unsigned addr) {
    asm volatile("ldmatrix.sync.aligned.m8n8.x4.shared.b16 {%0,%1,%2,%3},[%4];\n"
                 : "=r"(r0), "=r"(r1), "=r"(r2), "=r"(r3) : "r"(addr));
}

// ---------------- mask dtype sniff + convert + bit-pack (multi-block) ----------------
__global__ void mask_convert(const unsigned int* __restrict__ w, int n) {
    __shared__ int not01, not0f;
    if (threadIdx.x == 0) { not01 = 0; not0f = 0; }
    __syncthreads();
    int b01 = 0, b0f = 0;
    for (int i = threadIdx.x; i < 2048; i += blockDim.x) {
        unsigned v = w[i];
        if (v > 1u) b01 = 1;
        if (v != 0u && v != 0x3F800000u) b0f = 1;
    }
    if (b01) atomicOr(&not01, 1);
    if (b0f) atomicOr(&not0f, 1);
    __syncthreads();
    int mode = (!not01) ? 1 : ((!not0f) ? 2 : 0); // 1=int32, 2=float32, 0=uint8
    int gid = blockIdx.x * blockDim.x + threadIdx.x;
    int stride = gridDim.x * blockDim.x;
    for (int wi = gid; wi < n / 32; wi += stride) {
        unsigned bits = 0;
        for (int k = 0; k < 32; k++) {
            int i = wi * 32 + k;
            int v;
            if (mode == 1)      v = (((const int*)w)[i] != 0);
            else if (mode == 2) v = (((const float*)w)[i] != 0.0f);
            else                v = (((const unsigned char*)w)[i] != 0);
            g_mask[i] = v;
            bits |= (v ? 1u : 0u) << k;
        }
        g_mbits[wi] = bits;
    }
}

__global__ void bias_init() {
    int i = blockIdx.x * blockDim.x + threadIdx.x;
    if (i < M) g_bias[i] = logf(expf(-(float)i) + 1e-12f);
}

// ---------------- pre-round inputs to fp16 ----------------
__global__ void prep_round(const float* __restrict__ X,
                           const float* __restrict__ Wq, const float* __restrict__ Wk,
                           const float* __restrict__ Wv, const float* __restrict__ Wo) {
    int gid = blockIdx.x * blockDim.x + threadIdx.x;
    int stride = gridDim.x * blockDim.x;
    for (int i = gid; i < NTOK * DMODEL; i += stride) g_x[i] = __float2half_rn(X[i]);
    for (int i = gid; i < DMODEL * DMODEL; i += stride) {
        g_wq[i] = __float2half_rn(Wq[i]);
        g_wk[i] = __float2half_rn(Wk[i]);
        g_wv[i] = __float2half_rn(Wv[i]);
        g_wo[i] = __float2half_rn(Wo[i]);
    }
}

// ---------------- GEMM: 128x128 CTA tile, 32x64 warp, 256 thr, fp16, k-slab 64 ----------------
// 3-stage cp.async ring, 2 CTAs/SM for cross-CTA barrier overlap.
#define GK 64                              // halves per slab
#define GLDH 72                            // halves per padded row (144 B)
#define A_H (128 * GLDH)                   // A rows block
#define STG_H (256 * GLDH)                 // A 128 + B 128 rows = 18432 halves
#define GEMM_SMEM (3 * STG_H * 2)          // 110592 bytes -> 2 CTAs/SM

__global__ __launch_bounds__(256, 2) void qkv_gemm(
    const float* __restrict__ bq, const float* __restrict__ bk, const float* __restrict__ bv)
{
    extern __shared__ __half smh[];
    const int z = blockIdx.z;
    const __half* Wg   = (z == 0) ? g_wq : (z == 1) ? g_wk : g_wv;
    const float* bias  = (z == 0) ? bq : (z == 1) ? bk : bv;
    __half* out        = (z == 0) ? g_q : (z == 1) ? g_k : g_v;
    const float osc    = (z == 0) ? 0.125f : 1.0f;

    const int t = threadIdx.x, warp = t >> 5, lane = t & 31;
    const int q = lane & 3;
    const int wm = warp >> 1, wn = warp & 1;      // 4x2 warps; warp tile 32(m) x 64(n)
    const int n0 = blockIdx.y << 7, e0 = blockIdx.x << 7;

    const int arow  = (lane & 7) + ((lane >> 3) & 1) * 8;
    const int acolB = (lane >> 4) << 4;
    const int brow  = ((lane >> 4) << 3) + (lane & 7);
    const int bcolB = ((lane >> 3) & 1) << 4;

    auto stage = [&](int slab) {
        const int kk = slab * GK;
        __half* base = smh + (slab % 3) * STG_H;
        const unsigned aB = smem_u32(base), bB = aB + A_H * 2;
#pragma unroll
        for (int j = 0; j < 4; j++) {             // A: 128 rows x 8 chunks = 1024
            int ck = t + (j << 8);
            int r = ck >> 3, c = ck & 7;
            cp16(aB + (unsigned)(r * 144 + c * 16),
                 g_x + (size_t)(n0 + r) * DMODEL + kk + c * 8);
        }
#pragma unroll
        for (int j = 0; j < 4; j++) {             // B: 128 rows x 8 chunks = 1024
            int ck = t + (j << 8);
            int r = ck >> 3, c = ck & 7;
            cp16(bB + (unsigned)(r * 144 + c * 16),
                 Wg + (size_t)(e0 + r) * DMODEL + kk + c * 8);
        }
        cp_commit();
    };

    stage(0); stage(1);
    float acc[2][8][4] = {};
    for (int it = 0; it < 8; it++) {
        if (it < 7) cp_wait<1>(); else cp_wait<0>();
        __syncthreads();
        if (it + 2 < 8) stage(it + 2); else cp_commit();
        __half* base = smh + (it % 3) * STG_H;
        const unsigned xa = smem_u32(base) + (unsigned)((wm * 32 + arow) * 144 + acolB);
        const unsigned wa = smem_u32(base) + (unsigned)(A_H * 2 + (wn * 64 + brow) * 144 + bcolB);
#pragma unroll
        for (int kc = 0; kc < 4; kc++) {          // 4 x k16 = 64
            unsigned af[2][4], bf[8][2];
#pragma unroll
            for (int mf = 0; mf < 2; mf++)
                ldsm4(af[mf][0], af[mf][1], af[mf][2], af[mf][3],
                      xa + (unsigned)(mf * 16 * 144 + kc * 32));
#pragma unroll
            for (int np = 0; np < 4; np++) {
                unsigned r0, r1, r2, r3;
                ldsm4(r0, r1, r2, r3, wa + (unsigned)(np * 16 * 144 + kc * 32));
                bf[2 * np][0] = r0;     bf[2 * np][1] = r1;
                bf[2 * np + 1][0] = r2; bf[2 * np + 1][1] = r3;
            }
#pragma unroll
            for (int mf = 0; mf < 2; mf++)
#pragma unroll
                for (int nf = 0; nf < 8; nf++) mma16(acc[mf][nf], af[mf], bf[nf]);
        }
        __syncthreads();
    }

    // epilogue: fp16 out, [b,h,m,dh] (V transposed)
    const int g = lane >> 2;
#pragma unroll
    for (int mf = 0; mf < 2; mf++) {
        int ntA = n0 + wm * 32 + mf * 16 + g;
        int ntB = ntA + 8;
#pragma unroll
        for (int nf = 0; nf < 8; nf++) {
            int e = e0 + wn * 64 + nf * 8 + 2 * q;
            int hh = e >> 6, dh = e & 63;
            float b0v = bias[e], b1v = bias[e + 1];
            __half2 hA = __floats2half2_rn((acc[mf][nf][0] + b0v) * osc,
                                           (acc[mf][nf][1] + b1v) * osc);
            __half2 hB = __floats2half2_rn((acc[mf][nf][2] + b0v) * osc,
                                           (acc[mf][nf][3] + b1v) * osc);
            int bA = ntA >> 11, mA = ntA & 2047;
            int bB_ = ntB >> 11, mB = ntB & 2047;
            if (z == 2) {
                size_t baseA = ((size_t)bA * 8 + hh) * DHEAD;
                size_t baseB = ((size_t)bB_ * 8 + hh) * DHEAD;
                out[(baseA + dh) * M + mA]     = __low2half(hA);
                out[(baseA + dh + 1) * M + mA] = __high2half(hA);
                out[(baseB + dh) * M + mB]     = __low2half(hB);
                out[(baseB + dh + 1) * M + mB] = __high2half(hB);
            } else {
                *(__half2*)&out[(((size_t)bA * 8 + hh) * M + mA) * DHEAD + dh] = hA;
                *(__half2*)&out[(((size_t)bB_ * 8 + hh) * M + mB) * DHEAD + dh] = hB;
            }
        }
    }
}

// ---------------- output projection + mask ----------------
__global__ __launch_bounds__(256, 2) void oproj_gemm(
    const float* __restrict__ bo, float* __restrict__ out)
{
    extern __shared__ __half smh[];
    const int t = threadIdx.x, warp = t >> 5, lane = t & 31;
    const int q = lane & 3;
    const int wm = warp >> 1, wn = warp & 1;
    const int n0 = blockIdx.y << 7, e0 = blockIdx.x << 7;

    const int arow  = (lane & 7) + ((lane >> 3) & 1) * 8;
    const int acolB = (lane >> 4) << 4;
    const int brow  = ((lane >> 4) << 3) + (lane & 7);
    const int bcolB = ((lane >> 3) & 1) << 4;

    auto stage = [&](int slab) {
        const int kk = slab * GK;
        __half* base = smh + (slab % 3) * STG_H;
        const unsigned aB = smem_u32(base), bB = aB + A_H * 2;
#pragma unroll
        for (int j = 0; j < 4; j++) {
            int ck = t + (j << 8);
            int r = ck >> 3, c = ck & 7;
            cp16(aB + (unsigned)(r * 144 + c * 16),
                 g_ao + (size_t)(n0 + r) * DMODEL + kk + c * 8);
        }
#pragma unroll
        for (int j = 0; j < 4; j++) {
            int ck = t + (j << 8);
            int r = ck >> 3, c = ck & 7;
            cp16(bB + (unsigned)(r * 144 + c * 16),
                 g_wo + (size_t)(e0 + r) * DMODEL + kk + c * 8);
        }
        cp_commit();
    };

    stage(0); stage(1);
    float acc[2][8][4] = {};
    for (int it = 0; it < 8; it++) {
        if (it < 7) cp_wait<1>(); else cp_wait<0>();
        __syncthreads();
        if (it + 2 < 8) stage(it + 2); else cp_commit();
        __half* base = smh + (it % 3) * STG_H;
        const unsigned xa = smem_u32(base) + (unsigned)((wm * 32 + arow) * 144 + acolB);
        const unsigned wa = smem_u32(base) + (unsigned)(A_H * 2 + (wn * 64 + brow) * 144 + bcolB);
#pragma unroll
        for (int kc = 0; kc < 4; kc++) {
            unsigned af[2][4], bf[8][2];
#pragma unroll
            for (int mf = 0; mf < 2; mf++)
                ldsm4(af[mf][0], af[mf][1], af[mf][2], af[mf][3],
                      xa + (unsigned)(mf * 16 * 144 + kc * 32));
#pragma unroll
            for (int np = 0; np < 4; np++) {
                unsigned r0, r1, r2, r3;
                ldsm4(r0, r1, r2, r3, wa + (unsigned)(np * 16 * 144 + kc * 32));
                bf[2 * np][0] = r0;     bf[2 * np][1] = r1;
                bf[2 * np + 1][0] = r2; bf[2 * np + 1][1] = r3;
            }
#pragma unroll
            for (int mf = 0; mf < 2; mf++)
#pragma unroll
                for (int nf = 0; nf < 8; nf++) mma16(acc[mf][nf], af[mf], bf[nf]);
        }
        __syncthreads();
    }

    const int g = lane >> 2;
#pragma unroll
    for (int mf = 0; mf < 2; mf++) {
        int ntA = n0 + wm * 32 + mf * 16 + g;
        int ntB = ntA + 8;
        float mkA = (float)g_mask[ntA];
        float mkB = (float)g_mask[ntB];
#pragma unroll
        for (int nf = 0; nf < 8; nf++) {
            int e = e0 + wn * 64 + nf * 8 + 2 * q;
            float b0v = bo[e], b1v = bo[e + 1];
            float2 rA = make_float2((acc[mf][nf][0] + b0v) * mkA,
                                    (acc[mf][nf][1] + b1v) * mkA);
            float2 rB = make_float2((acc[mf][nf][2] + b0v) * mkB,
                                    (acc[mf][nf][3] + b1v) * mkB);
            *(float2*)&out[(size_t)ntA * DMODEL + e] = rA;
            *(float2*)&out[(size_t)ntB * DMODEL + e] = rB;
        }
    }
}

// ---------------- attention: banded fp16, 128-row Q tile, 16 rows/warp, 2 blocks/SM ----------------
#define KLDH 72   // halves, 144 B rows
#define ATT_SMEM (27648 * 2 + 256 * 4 + 64 * 4)   // 56576

__global__ __launch_bounds__(256, 2) void attn_kernel() {
    extern __shared__ __half smh[];
    __half* Ks0    = smh;                          // [2][64][72]
    __half* Vt0    = smh + 2 * 64 * KLDH;          // [2][64][72], row=d, col=key
    __half* Pw_all = smh + 4 * 64 * KLDH;          // [8][16][72]
    float*  sbias  = (float*)(smh + 4 * 64 * KLDH + 8 * 16 * KLDH);
    unsigned* mbw  = (unsigned*)(sbias + 256);

    const int t = threadIdx.x, warp = t >> 5, lane = t & 31;
    const int g = lane >> 2, q = lane & 3;
    const int bh = blockIdx.y, b = bh >> 3, hh = bh & 7;
    const int m0 = blockIdx.x << 7;
    const __half* qb = g_q + (size_t)bh * M * DHEAD;
    const __half* kb = g_k + (size_t)bh * M * DHEAD;
    const __half* vbT = g_v + (size_t)bh * DHEAD * M;

    sbias[t] = g_bias[t];
    if (t < 64) mbw[t] = g_mbits[b * 64 + t];

    const int mw = m0 + warp * 16;
    unsigned qf[4][4];
    {
        const __half* q0 = qb + (size_t)(mw + g) * DHEAD;
        const __half* q1 = qb + (size_t)(mw + g + 8) * DHEAD;
#pragma unroll
        for (int kc = 0; kc < 4; kc++) {
            qf[kc][0] = *(const unsigned*)&q0[kc * 16 + 2 * q];
            qf[kc][1] = *(const unsigned*)&q1[kc * 16 + 2 * q];
            qf[kc][2] = *(const unsigned*)&q0[kc * 16 + 8 + 2 * q];
            qf[kc][3] = *(const unsigned*)&q1[kc * 16 + 8 + 2 * q];
        }
    }

    float oacc[8][4] = {};
    float l0 = 0.0f, l1 = 0.0f;

    const int brow  = ((lane >> 4) << 3) + (lane & 7);
    const int bcolB = ((lane >> 3) & 1) << 4;
    const unsigned kfb = (unsigned)(brow * 144 + bcolB);
    const int prow  = (lane & 7) + ((lane >> 3) & 1) * 8;
    const int pcolB = (lane >> 4) << 4;
    __half* Pw = Pw_all + warp * 16 * KLDH;
    const unsigned pa_base = smem_u32(Pw) + (unsigned)(prow * 144 + pcolB);
    const unsigned ks_base = smem_u32(Ks0);
    const unsigned vs_base = smem_u32(Vt0);

    auto stage = [&](int tile, int buf) {
        const __half* ksrc = kb + (size_t)(tile * 64) * DHEAD;
        const __half* vsrc = vbT + tile * 64;
        __half* kd = Ks0 + buf * 64 * KLDH;
        __half* vd = Vt0 + buf * 64 * KLDH;
#pragma unroll
        for (int j = 0; j < 2; j++) {
            int ck = t + j * 256;
            int row = ck >> 3, c = ck & 7;
            cp16(smem_u32(kd) + (unsigned)(row * 144 + c * 16), ksrc + row * 64 + c * 8);
            cp16(smem_u32(vd) + (unsigned)(row * 144 + c * 16), vsrc + (size_t)row * M + c * 8);
        }
    };

    const int tlo = max(0, (m0 >> 6) - 1);
    const int thi = min(M / 64 - 1, (m0 >> 6) + 2);

    stage(tlo, 0); cp_commit();

    for (int tile = tlo; tile <= thi; tile++) {
        const int bufi = (tile - tlo) & 1;
        if (tile < thi) { stage(tile + 1, bufi ^ 1); cp_commit(); cp_wait<1>(); }
        else cp_wait<0>();
        __syncthreads();

        const int n0 = tile << 6;
        if (n0 <= mw + 79 && n0 + 63 >= mw - 64) {
            const unsigned kbuf = ks_base + bufi * (64 * 144) + kfb;
            const unsigned vbuf = vs_base + bufi * (64 * 144) + kfb;

            float sacc[8][4] = {};
#pragma unroll
            for (int kc = 0; kc < 4; kc++) {
                unsigned bb[8][2];
#pragma unroll
                for (int np = 0; np < 4; np++) {
                    unsigned r0, r1, r2, r3;
                    ldsm4(r0, r1, r2, r3, kbuf + (unsigned)(np * 16 * 144 + kc * 32));
                    bb[2 * np][0] = r0;     bb[2 * np][1] = r1;
                    bb[2 * np + 1][0] = r2; bb[2 * np + 1][1] = r3;
                }
#pragma unroll
                for (int nf = 0; nf < 8; nf++) mma16(sacc[nf], qf[kc], bb[nf]);
            }

            const unsigned w0 = mbw[tile * 2], w1 = mbw[tile * 2 + 1];
            const int mg0 = mw + g, mg1 = mg0 + 8;
#pragma unroll
            for (int nf = 0; nf < 8; nf++) {
                int off = nf * 8 + 2 * q;
                unsigned wsel = (nf < 4) ? w0 : w1;
                int sh = off & 31;
                bool v0m = (wsel >> sh) & 1;
                bool v1m = (wsel >> (sh + 1)) & 1;
                int n_ = n0 + off;
                int d00 = abs(mg0 - n_), d01 = abs(mg0 - n_ - 1);
                int d10 = abs(mg1 - n_), d11 = abs(mg1 - n_ - 1);
                float p0 = v0m ? __expf(sacc[nf][0] + sbias[d00]) : 0.0f;
                float p1 = v1m ? __expf(sacc[nf][1] + sbias[d01]) : 0.0f;
                float p2 = v0m ? __expf(sacc[nf][2] + sbias[d10]) : 0.0f;
                float p3 = v1m ? __expf(sacc[nf][3] + sbias[d11]) : 0.0f;
                __half2 h01 = __floats2half2_rn(p0, p1);
                __half2 h23 = __floats2half2_rn(p2, p3);
                l0 += __low2float(h01) + __high2float(h01);
                l1 += __low2float(h23) + __high2float(h23);
                *(__half2*)&Pw[g * KLDH + off]       = h01;
                *(__half2*)&Pw[(g + 8) * KLDH + off] = h23;
            }
            __syncwarp();

#pragma unroll
            for (int kc = 0; kc < 4; kc++) {
                unsigned pa[4];
                ldsm4(pa[0], pa[1], pa[2], pa[3], pa_base + (unsigned)(kc * 32));
                unsigned vv[8][2];
#pragma unroll
                for (int dp = 0; dp < 4; dp++) {
                    unsigned r0, r1, r2, r3;
                    ldsm4(r0, r1, r2, r3, vbuf + (unsigned)(dp * 16 * 144 + kc * 32));
                    vv[2 * dp][0] = r0;     vv[2 * dp][1] = r1;
                    vv[2 * dp + 1][0] = r2; vv[2 * dp + 1][1] = r3;
                }
#pragma unroll
                for (int df = 0; df < 8; df++) mma16(oacc[df], pa, vv[df]);
            }
        }
        __syncthreads();
    }

    l0 += __shfl_xor_sync(0xffffffffu, l0, 1);
    l0 += __shfl_xor_sync(0xffffffffu, l0, 2);
    l1 += __shfl_xor_sync(0xffffffffu, l1, 1);
    l1 += __shfl_xor_sync(0xffffffffu, l1, 2);
    float i0 = 1.0f / fmaxf(l0, 1e-30f);
    float i1 = 1.0f / fmaxf(l1, 1e-30f);
    __half* ob = g_ao + (size_t)b * M * DMODEL + (size_t)hh * DHEAD;
#pragma unroll
    for (int df = 0; df < 8; df++) {
        *(__half2*)&ob[(size_t)(mw + g) * DMODEL + df * 8 + 2 * q] =
            __floats2half2_rn(oacc[df][0] * i0, oacc[df][1] * i0);
        *(__half2*)&ob[(size_t)(mw + g + 8) * DMODEL + df * 8 + 2 * q] =
            __floats2half2_rn(oacc[df][2] * i1, oacc[df][3] * i1);
    }
}

// ---------------- launch ----------------
extern "C" void kernel_launch(void* const* d_in, const int* in_sizes, int n_in,
                              void* d_out, int out_size) {
    const float* h  = (const float*)d_in[0];
    const void*  pm = d_in[1];
    const float* Wq = (const float*)d_in[2];
    const float* bq = (const float*)d_in[3];
    const float* Wk = (const float*)d_in[4];
    const float* bk = (const float*)d_in[5];
    const float* Wv = (const float*)d_in[6];
    const float* bv = (const float*)d_in[7];
    const float* Wo = (const float*)d_in[8];
    const float* bo = (const float*)d_in[9];
    float* out = (float*)d_out;

    mask_convert<<<32, 256>>>((const unsigned int*)pm, NTOK);
    bias_init<<<8, 256>>>();
    prep_round<<<512, 256>>>(h, Wq, Wk, Wv, Wo);

    cudaFuncSetAttribute(qkv_gemm, cudaFuncAttributeMaxDynamicSharedMemorySize, GEMM_SMEM);
    cudaFuncSetAttribute(oproj_gemm, cudaFuncAttributeMaxDynamicSharedMemorySize, GEMM_SMEM);
    cudaFuncSetAttribute(attn_kernel, cudaFuncAttributeMaxDynamicSharedMemorySize, ATT_SMEM);

    dim3 g1(DMODEL / 128, NTOK / 128, 3);
    qkv_gemm<<<g1, 256, GEMM_SMEM>>>(bq, bk, bv);

    dim3 g2(M / 128, BH);
    attn_kernel<<<g2, 256, ATT_SMEM>>>();

    dim3 g3(DMODEL / 128, NTOK / 128);
    oproj_gemm<<<g3, 256, GEMM_SMEM>>>(bo, out);
}

// round 15
// speedup vs baseline: 1.0303x; 1.0303x over previous
#include <cuda_runtime.h>
#include <cuda_fp16.h>
#include <math.h>

#define B 4
#define M 2048
#define DMODEL 512
#define NHEAD 8
#define DHEAD 64
#define NTOK (B*M)          // 8192
#define BH (B*NHEAD)        // 32

// ---------------- scratch (device globals) ----------------
__device__ __half g_x[NTOK * DMODEL];     // h, fp16
__device__ __half g_wq[DMODEL * DMODEL];  // weights, fp16
__device__ __half g_wk[DMODEL * DMODEL];
__device__ __half g_wv[DMODEL * DMODEL];
__device__ __half g_wo[DMODEL * DMODEL];
__device__ __half g_q[BH * M * DHEAD];    // [b,h,m,dh], fp16, pre-scaled 1/8
__device__ __half g_k[BH * M * DHEAD];    // [b,h,m,dh] fp16
__device__ __half g_v[BH * DHEAD * M];    // [b,h,dh,m] TRANSPOSED, fp16
__device__ __half g_ao[NTOK * DMODEL];    // attention output [b,m,d], fp16
__device__ float  g_bias[M];              // log(exp(-d)+1e-12)
__device__ int    g_mask[NTOK];
__device__ unsigned g_mbits[NTOK / 32];   // packed mask bits

// ---------------- ptx helpers ----------------
__device__ __forceinline__ unsigned smem_u32(const void* p) {
    return (unsigned)__cvta_generic_to_shared(p);
}
__device__ __forceinline__ void cp16(unsigned d, const void* s) {
    asm volatile("cp.async.cg.shared.global [%0],[%1],16;\n" :: "r"(d), "l"(s) : "memory");
}
__device__ __forceinline__ void cp_commit() {
    asm volatile("cp.async.commit_group;\n" ::: "memory");
}
template<int N> __device__ __forceinline__ void cp_wait() {
    asm volatile("cp.async.wait_group %0;\n" :: "n"(N) : "memory");
}
// fp16 mma: D(f32) += A(f16 4reg) * B(f16 2reg), m16n8k16 row.col
__device__ __forceinline__ void mma16(float* c, const unsigned* a, const unsigned* b) {
    asm volatile(
        "mma.sync.aligned.m16n8k16.row.col.f32.f16.f16.f32 "
        "{%0,%1,%2,%3},{%4,%5,%6,%7},{%8,%9},{%0,%1,%2,%3};\n"
        : "+f"(c[0]), "+f"(c[1]), "+f"(c[2]), "+f"(c[3])
        : "r"(a[0]), "r"(a[1]), "r"(a[2]), "r"(a[3]), "r"(b[0]), "r"(b[1]));
}
__device__ __forceinline__ void ldsm4(unsigned& r0, unsigned& r1, unsigned& r2, unsigned& r3,
                                      unsigned addr) {
    asm volatile("ldmatrix.sync.aligned.m8n8.x4.shared.b16 {%0,%1,%2,%3},[%4];\n"
                 : "=r"(r0), "=r"(r1), "=r"(r2), "=r"(r3) : "r"(addr));
}

// ---------------- mask dtype sniff + convert + bit-pack + bias init ----------------
__global__ void mask_convert(const unsigned int* __restrict__ w, int n) {
    __shared__ int not01, not0f;
    if (threadIdx.x == 0) { not01 = 0; not0f = 0; }
    __syncthreads();
    int b01 = 0, b0f = 0;
    for (int i = threadIdx.x; i < 2048; i += blockDim.x) {
        unsigned v = w[i];
        if (v > 1u) b01 = 1;
        if (v != 0u && v != 0x3F800000u) b0f = 1;
    }
    if (b01) atomicOr(&not01, 1);
    if (b0f) atomicOr(&not0f, 1);
    __syncthreads();
    int mode = (!not01) ? 1 : ((!not0f) ? 2 : 0); // 1=int32, 2=float32, 0=uint8
    int gid = blockIdx.x * blockDim.x + threadIdx.x;
    int stride = gridDim.x * blockDim.x;
    for (int wi = gid; wi < n / 32; wi += stride) {
        unsigned bits = 0;
        for (int k = 0; k < 32; k++) {
            int i = wi * 32 + k;
            int v;
            if (mode == 1)      v = (((const int*)w)[i] != 0);
            else if (mode == 2) v = (((const float*)w)[i] != 0.0f);
            else                v = (((const unsigned char*)w)[i] != 0);
            g_mask[i] = v;
            bits |= (v ? 1u : 0u) << k;
        }
        g_mbits[wi] = bits;
    }
    for (int i = gid; i < M; i += stride)
        g_bias[i] = logf(expf(-(float)i) + 1e-12f);
}

// ---------------- pre-round inputs to fp16 ----------------
__global__ void prep_round(const float* __restrict__ X,
                           const float* __restrict__ Wq, const float* __restrict__ Wk,
                           const float* __restrict__ Wv, const float* __restrict__ Wo) {
    int gid = blockIdx.x * blockDim.x + threadIdx.x;
    int stride = gridDim.x * blockDim.x;
    for (int i = gid; i < NTOK * DMODEL; i += stride) g_x[i] = __float2half_rn(X[i]);
    for (int i = gid; i < DMODEL * DMODEL; i += stride) {
        g_wq[i] = __float2half_rn(Wq[i]);
        g_wk[i] = __float2half_rn(Wk[i]);
        g_wv[i] = __float2half_rn(Wv[i]);
        g_wo[i] = __float2half_rn(Wo[i]);
    }
}

// ---------------- GEMM: 128x128 CTA tile, 32x64 warp, 256 thr, fp16, k-slab 64 ----------------
#define GK 64
#define GLDH 72
#define A_H (128 * GLDH)
#define STG_H (256 * GLDH)                 // 18432 halves
#define GEMM_SMEM (3 * STG_H * 2)          // 110592 bytes -> 2 CTAs/SM

__global__ __launch_bounds__(256, 2) void qkv_gemm(
    const float* __restrict__ bq, const float* __restrict__ bk, const float* __restrict__ bv)
{
    extern __shared__ __half smh[];
    const int z = blockIdx.z;
    const __half* Wg   = (z == 0) ? g_wq : (z == 1) ? g_wk : g_wv;
    const float* bias  = (z == 0) ? bq : (z == 1) ? bk : bv;
    __half* out        = (z == 0) ? g_q : (z == 1) ? g_k : g_v;
    const float osc    = (z == 0) ? 0.125f : 1.0f;

    const int t = threadIdx.x, warp = t >> 5, lane = t & 31;
    const int q = lane & 3;
    const int wm = warp >> 1, wn = warp & 1;
    const int n0 = blockIdx.y << 7, e0 = blockIdx.x << 7;

    const int arow  = (lane & 7) + ((lane >> 3) & 1) * 8;
    const int acolB = (lane >> 4) << 4;
    const int brow  = ((lane >> 4) << 3) + (lane & 7);
    const int bcolB = ((lane >> 3) & 1) << 4;

    auto stage = [&](int slab) {
        const int kk = slab * GK;
        __half* base = smh + (slab % 3) * STG_H;
        const unsigned aB = smem_u32(base), bB = aB + A_H * 2;
#pragma unroll
        for (int j = 0; j < 4; j++) {
            int ck = t + (j << 8);
            int r = ck >> 3, c = ck & 7;
            cp16(aB + (unsigned)(r * 144 + c * 16),
                 g_x + (size_t)(n0 + r) * DMODEL + kk + c * 8);
        }
#pragma unroll
        for (int j = 0; j < 4; j++) {
            int ck = t + (j << 8);
            int r = ck >> 3, c = ck & 7;
            cp16(bB + (unsigned)(r * 144 + c * 16),
                 Wg + (size_t)(e0 + r) * DMODEL + kk + c * 8);
        }
        cp_commit();
    };

    stage(0); stage(1);
    float acc[2][8][4] = {};
    for (int it = 0; it < 8; it++) {
        if (it < 7) cp_wait<1>(); else cp_wait<0>();
        __syncthreads();
        if (it + 2 < 8) stage(it + 2); else cp_commit();
        __half* base = smh + (it % 3) * STG_H;
        const unsigned xa = smem_u32(base) + (unsigned)((wm * 32 + arow) * 144 + acolB);
        const unsigned wa = smem_u32(base) + (unsigned)(A_H * 2 + (wn * 64 + brow) * 144 + bcolB);
#pragma unroll
        for (int kc = 0; kc < 4; kc++) {
            unsigned af[2][4], bf[8][2];
#pragma unroll
            for (int mf = 0; mf < 2; mf++)
                ldsm4(af[mf][0], af[mf][1], af[mf][2], af[mf][3],
                      xa + (unsigned)(mf * 16 * 144 + kc * 32));
#pragma unroll
            for (int np = 0; np < 4; np++) {
                unsigned r0, r1, r2, r3;
                ldsm4(r0, r1, r2, r3, wa + (unsigned)(np * 16 * 144 + kc * 32));
                bf[2 * np][0] = r0;     bf[2 * np][1] = r1;
                bf[2 * np + 1][0] = r2; bf[2 * np + 1][1] = r3;
            }
#pragma unroll
            for (int mf = 0; mf < 2; mf++)
#pragma unroll
                for (int nf = 0; nf < 8; nf++) mma16(acc[mf][nf], af[mf], bf[nf]);
        }
        __syncthreads();
    }

    const int g = lane >> 2;
#pragma unroll
    for (int mf = 0; mf < 2; mf++) {
        int ntA = n0 + wm * 32 + mf * 16 + g;
        int ntB = ntA + 8;
#pragma unroll
        for (int nf = 0; nf < 8; nf++) {
            int e = e0 + wn * 64 + nf * 8 + 2 * q;
            int hh = e >> 6, dh = e & 63;
            float b0v = bias[e], b1v = bias[e + 1];
            __half2 hA = __floats2half2_rn((acc[mf][nf][0] + b0v) * osc,
                                           (acc[mf][nf][1] + b1v) * osc);
            __half2 hB = __floats2half2_rn((acc[mf][nf][2] + b0v) * osc,
                                           (acc[mf][nf][3] + b1v) * osc);
            int bA = ntA >> 11, mA = ntA & 2047;
            int bB_ = ntB >> 11, mB = ntB & 2047;
            if (z == 2) {
                size_t baseA = ((size_t)bA * 8 + hh) * DHEAD;
                size_t baseB = ((size_t)bB_ * 8 + hh) * DHEAD;
                out[(baseA + dh) * M + mA]     = __low2half(hA);
                out[(baseA + dh + 1) * M + mA] = __high2half(hA);
                out[(baseB + dh) * M + mB]     = __low2half(hB);
                out[(baseB + dh + 1) * M + mB] = __high2half(hB);
            } else {
                *(__half2*)&out[(((size_t)bA * 8 + hh) * M + mA) * DHEAD + dh] = hA;
                *(__half2*)&out[(((size_t)bB_ * 8 + hh) * M + mB) * DHEAD + dh] = hB;
            }
        }
    }
}

// ---------------- output projection + mask ----------------
__global__ __launch_bounds__(256, 2) void oproj_gemm(
    const float* __restrict__ bo, float* __restrict__ out)
{
    extern __shared__ __half smh[];
    const int t = threadIdx.x, warp = t >> 5, lane = t & 31;
    const int q = lane & 3;
    const int wm = warp >> 1, wn = warp & 1;
    const int n0 = blockIdx.y << 7, e0 = blockIdx.x << 7;

    const int arow  = (lane & 7) + ((lane >> 3) & 1) * 8;
    const int acolB = (lane >> 4) << 4;
    const int brow  = ((lane >> 4) << 3) + (lane & 7);
    const int bcolB = ((lane >> 3) & 1) << 4;

    auto stage = [&](int slab) {
        const int kk = slab * GK;
        __half* base = smh + (slab % 3) * STG_H;
        const unsigned aB = smem_u32(base), bB = aB + A_H * 2;
#pragma unroll
        for (int j = 0; j < 4; j++) {
            int ck = t + (j << 8);
            int r = ck >> 3, c = ck & 7;
            cp16(aB + (unsigned)(r * 144 + c * 16),
                 g_ao + (size_t)(n0 + r) * DMODEL + kk + c * 8);
        }
#pragma unroll
        for (int j = 0; j < 4; j++) {
            int ck = t + (j << 8);
            int r = ck >> 3, c = ck & 7;
            cp16(bB + (unsigned)(r * 144 + c * 16),
                 g_wo + (size_t)(e0 + r) * DMODEL + kk + c * 8);
        }
        cp_commit();
    };

    stage(0); stage(1);
    float acc[2][8][4] = {};
    for (int it = 0; it < 8; it++) {
        if (it < 7) cp_wait<1>(); else cp_wait<0>();
        __syncthreads();
        if (it + 2 < 8) stage(it + 2); else cp_commit();
        __half* base = smh + (it % 3) * STG_H;
        const unsigned xa = smem_u32(base) + (unsigned)((wm * 32 + arow) * 144 + acolB);
        const unsigned wa = smem_u32(base) + (unsigned)(A_H * 2 + (wn * 64 + brow) * 144 + bcolB);
#pragma unroll
        for (int kc = 0; kc < 4; kc++) {
            unsigned af[2][4], bf[8][2];
#pragma unroll
            for (int mf = 0; mf < 2; mf++)
                ldsm4(af[mf][0], af[mf][1], af[mf][2], af[mf][3],
                      xa + (unsigned)(mf * 16 * 144 + kc * 32));
#pragma unroll
            for (int np = 0; np < 4; np++) {
                unsigned r0, r1, r2, r3;
                ldsm4(r0, r1, r2, r3, wa + (unsigned)(np * 16 * 144 + kc * 32));
                bf[2 * np][0] = r0;     bf[2 * np][1] = r1;
                bf[2 * np + 1][0] = r2; bf[2 * np + 1][1] = r3;
            }
#pragma unroll
            for (int mf = 0; mf < 2; mf++)
#pragma unroll
                for (int nf = 0; nf < 8; nf++) mma16(acc[mf][nf], af[mf], bf[nf]);
        }
        __syncthreads();
    }

    const int g = lane >> 2;
#pragma unroll
    for (int mf = 0; mf < 2; mf++) {
        int ntA = n0 + wm * 32 + mf * 16 + g;
        int ntB = ntA + 8;
        float mkA = (float)g_mask[ntA];
        float mkB = (float)g_mask[ntB];
#pragma unroll
        for (int nf = 0; nf < 8; nf++) {
            int e = e0 + wn * 64 + nf * 8 + 2 * q;
            float b0v = bo[e], b1v = bo[e + 1];
            float2 rA = make_float2((acc[mf][nf][0] + b0v) * mkA,
                                    (acc[mf][nf][1] + b1v) * mkA);
            float2 rB = make_float2((acc[mf][nf][2] + b0v) * mkB,
                                    (acc[mf][nf][3] + b1v) * mkB);
            *(float2*)&out[(size_t)ntA * DMODEL + e] = rA;
            *(float2*)&out[(size_t)ntB * DMODEL + e] = rB;
        }
    }
}

// ---------------- attention: banded fp16, P in registers (C-frag == A-frag) ----------------
#define KLDH 72   // halves, 144 B rows
// halves: K 2*64*72 + V 2*64*72 = 18432; + bias 256 f32 + mbits 64 u32
#define ATT_SMEM (18432 * 2 + 256 * 4 + 64 * 4)   // 38144

__global__ __launch_bounds__(256, 2) void attn_kernel() {
    extern __shared__ __half smh[];
    __half* Ks0    = smh;                          // [2][64][72]
    __half* Vt0    = smh + 2 * 64 * KLDH;          // [2][64][72], row=d, col=key
    float*  sbias  = (float*)(smh + 4 * 64 * KLDH);
    unsigned* mbw  = (unsigned*)(sbias + 256);

    const int t = threadIdx.x, warp = t >> 5, lane = t & 31;
    const int g = lane >> 2, q = lane & 3;
    const int bh = blockIdx.y, b = bh >> 3, hh = bh & 7;
    const int m0 = blockIdx.x << 7;
    const __half* qb = g_q + (size_t)bh * M * DHEAD;
    const __half* kb = g_k + (size_t)bh * M * DHEAD;
    const __half* vbT = g_v + (size_t)bh * DHEAD * M;

    sbias[t] = g_bias[t];
    if (t < 64) mbw[t] = g_mbits[b * 64 + t];

    const int mw = m0 + warp * 16;
    unsigned qf[4][4];
    {
        const __half* q0 = qb + (size_t)(mw + g) * DHEAD;
        const __half* q1 = qb + (size_t)(mw + g + 8) * DHEAD;
#pragma unroll
        for (int kc = 0; kc < 4; kc++) {
            qf[kc][0] = *(const unsigned*)&q0[kc * 16 + 2 * q];
            qf[kc][1] = *(const unsigned*)&q1[kc * 16 + 2 * q];
            qf[kc][2] = *(const unsigned*)&q0[kc * 16 + 8 + 2 * q];
            qf[kc][3] = *(const unsigned*)&q1[kc * 16 + 8 + 2 * q];
        }
    }

    float oacc[8][4] = {};
    float l0 = 0.0f, l1 = 0.0f;

    const int brow  = ((lane >> 4) << 3) + (lane & 7);
    const int bcolB = ((lane >> 3) & 1) << 4;
    const unsigned kfb = (unsigned)(brow * 144 + bcolB);
    const unsigned ks_base = smem_u32(Ks0);
    const unsigned vs_base = smem_u32(Vt0);

    auto stage = [&](int tile, int buf) {
        const __half* ksrc = kb + (size_t)(tile * 64) * DHEAD;
        const __half* vsrc = vbT + tile * 64;
        __half* kd = Ks0 + buf * 64 * KLDH;
        __half* vd = Vt0 + buf * 64 * KLDH;
#pragma unroll
        for (int j = 0; j < 2; j++) {
            int ck = t + j * 256;
            int row = ck >> 3, c = ck & 7;
            cp16(smem_u32(kd) + (unsigned)(row * 144 + c * 16), ksrc + row * 64 + c * 8);
            cp16(smem_u32(vd) + (unsigned)(row * 144 + c * 16), vsrc + (size_t)row * M + c * 8);
        }
    };

    const int tlo = max(0, (m0 >> 6) - 1);
    const int thi = min(M / 64 - 1, (m0 >> 6) + 2);

    stage(tlo, 0); cp_commit();

    for (int tile = tlo; tile <= thi; tile++) {
        const int bufi = (tile - tlo) & 1;
        if (tile < thi) { stage(tile + 1, bufi ^ 1); cp_commit(); cp_wait<1>(); }
        else cp_wait<0>();
        __syncthreads();

        const int n0 = tile << 6;
        if (n0 <= mw + 79 && n0 + 63 >= mw - 64) {
            const unsigned kbuf = ks_base + bufi * (64 * 144) + kfb;
            const unsigned vbuf = vs_base + bufi * (64 * 144) + kfb;

            // ---- S = Q K^T ----
            float sacc[8][4] = {};
#pragma unroll
            for (int kc = 0; kc < 4; kc++) {
                unsigned bb[8][2];
#pragma unroll
                for (int np = 0; np < 4; np++) {
                    unsigned r0, r1, r2, r3;
                    ldsm4(r0, r1, r2, r3, kbuf + (unsigned)(np * 16 * 144 + kc * 32));
                    bb[2 * np][0] = r0;     bb[2 * np][1] = r1;
                    bb[2 * np + 1][0] = r2; bb[2 * np + 1][1] = r3;
                }
#pragma unroll
                for (int nf = 0; nf < 8; nf++) mma16(sacc[nf], qf[kc], bb[nf]);
            }

            // ---- softmax (static max): P stays in registers as PV A-frags ----
            const unsigned w0 = mbw[tile * 2], w1 = mbw[tile * 2 + 1];
            const int mg0 = mw + g, mg1 = mg0 + 8;
            unsigned pA[8], pB[8];
#pragma unroll
            for (int nf = 0; nf < 8; nf++) {
                int off = nf * 8 + 2 * q;
                unsigned wsel = (nf < 4) ? w0 : w1;
                int sh = off & 31;
                bool v0m = (wsel >> sh) & 1;
                bool v1m = (wsel >> (sh + 1)) & 1;
                int n_ = n0 + off;
                int d00 = abs(mg0 - n_), d01 = abs(mg0 - n_ - 1);
                int d10 = abs(mg1 - n_), d11 = abs(mg1 - n_ - 1);
                float p0 = v0m ? __expf(sacc[nf][0] + sbias[d00]) : 0.0f;
                float p1 = v1m ? __expf(sacc[nf][1] + sbias[d01]) : 0.0f;
                float p2 = v0m ? __expf(sacc[nf][2] + sbias[d10]) : 0.0f;
                float p3 = v1m ? __expf(sacc[nf][3] + sbias[d11]) : 0.0f;
                __half2 h01 = __floats2half2_rn(p0, p1);
                __half2 h23 = __floats2half2_rn(p2, p3);
                l0 += __low2float(h01) + __high2float(h01);
                l1 += __low2float(h23) + __high2float(h23);
                pA[nf] = *(unsigned*)&h01;
                pB[nf] = *(unsigned*)&h23;
            }

            // ---- O += P V (P A-frags direct from registers) ----
#pragma unroll
            for (int kc = 0; kc < 4; kc++) {
                unsigned pa[4];
                pa[0] = pA[2 * kc];     // row g,   k = 16kc + 2q,2q+1
                pa[1] = pB[2 * kc];     // row g+8, same k
                pa[2] = pA[2 * kc + 1]; // row g,   k = 16kc + 8 + 2q,2q+1
                pa[3] = pB[2 * kc + 1]; // row g+8, same k
                unsigned vv[8][2];
#pragma unroll
                for (int dp = 0; dp < 4; dp++) {
                    unsigned r0, r1, r2, r3;
                    ldsm4(r0, r1, r2, r3, vbuf + (unsigned)(dp * 16 * 144 + kc * 32));
                    vv[2 * dp][0] = r0;     vv[2 * dp][1] = r1;
                    vv[2 * dp + 1][0] = r2; vv[2 * dp + 1][1] = r3;
                }
#pragma unroll
                for (int df = 0; df < 8; df++) mma16(oacc[df], pa, vv[df]);
            }
        }
        __syncthreads();
    }

    l0 += __shfl_xor_sync(0xffffffffu, l0, 1);
    l0 += __shfl_xor_sync(0xffffffffu, l0, 2);
    l1 += __shfl_xor_sync(0xffffffffu, l1, 1);
    l1 += __shfl_xor_sync(0xffffffffu, l1, 2);
    float i0 = 1.0f / fmaxf(l0, 1e-30f);
    float i1 = 1.0f / fmaxf(l1, 1e-30f);
    __half* ob = g_ao + (size_t)b * M * DMODEL + (size_t)hh * DHEAD;
#pragma unroll
    for (int df = 0; df < 8; df++) {
        *(__half2*)&ob[(size_t)(mw + g) * DMODEL + df * 8 + 2 * q] =
            __floats2half2_rn(oacc[df][0] * i0, oacc[df][1] * i0);
        *(__half2*)&ob[(size_t)(mw + g + 8) * DMODEL + df * 8 + 2 * q] =
            __floats2half2_rn(oacc[df][2] * i1, oacc[df][3] * i1);
    }
}

// ---------------- launch ----------------
extern "C" void kernel_launch(void* const* d_in, const int* in_sizes, int n_in,
                              void* d_out, int out_size) {
    const float* h  = (const float*)d_in[0];
    const void*  pm = d_in[1];
    const float* Wq = (const float*)d_in[2];
    const float* bq = (const float*)d_in[3];
    const float* Wk = (const float*)d_in[4];
    const float* bk = (const float*)d_in[5];
    const float* Wv = (const float*)d_in[6];
    const float* bv = (const float*)d_in[7];
    const float* Wo = (const float*)d_in[8];
    const float* bo = (const float*)d_in[9];
    float* out = (float*)d_out;

    mask_convert<<<32, 256>>>((const unsigned int*)pm, NTOK);
    prep_round<<<512, 256>>>(h, Wq, Wk, Wv, Wo);

    cudaFuncSetAttribute(qkv_gemm, cudaFuncAttributeMaxDynamicSharedMemorySize, GEMM_SMEM);
    cudaFuncSetAttribute(oproj_gemm, cudaFuncAttributeMaxDynamicSharedMemorySize, GEMM_SMEM);
    cudaFuncSetAttribute(attn_kernel, cudaFuncAttributeMaxDynamicSharedMemorySize, ATT_SMEM);

    dim3 g1(DMODEL / 128, NTOK / 128, 3);
    qkv_gemm<<<g1, 256, GEMM_SMEM>>>(bq, bk, bv);

    dim3 g2(M / 128, BH);
    attn_kernel<<<g2, 256, ATT_SMEM>>>();

    dim3 g3(DMODEL / 128, NTOK / 128);
    oproj_gemm<<<g3, 256, GEMM_SMEM>>>(bo, out);
}

// round 16
// speedup vs baseline: 1.1041x; 1.0716x over previous
#include <cuda_runtime.h>
#include <cuda_fp16.h>
#include <math.h>

#define B 4
#define M 2048
#define DMODEL 512
#define NHEAD 8
#define DHEAD 64
#define NTOK (B*M)          // 8192
#define BH (B*NHEAD)        // 32

// ---------------- scratch (device globals) ----------------
__device__ __half g_x[NTOK * DMODEL];     // h, fp16
__device__ __half g_wq[DMODEL * DMODEL];  // weights, fp16
__device__ __half g_wk[DMODEL * DMODEL];
__device__ __half g_wv[DMODEL * DMODEL];
__device__ __half g_wo[DMODEL * DMODEL];
__device__ __half g_q[BH * M * DHEAD];    // [b,h,m,dh], fp16, pre-scaled 1/8
__device__ __half g_k[BH * M * DHEAD];    // [b,h,m,dh] fp16
__device__ __half g_v[BH * DHEAD * M];    // [b,h,dh,m] TRANSPOSED, fp16
__device__ __half g_ao[NTOK * DMODEL];    // attention output [b,m,d], fp16
__device__ int    g_mask[NTOK];
__device__ unsigned g_mbits[NTOK / 32];   // packed mask bits

// ---------------- ptx helpers ----------------
__device__ __forceinline__ unsigned smem_u32(const void* p) {
    return (unsigned)__cvta_generic_to_shared(p);
}
__device__ __forceinline__ void cp16(unsigned d, const void* s) {
    asm volatile("cp.async.cg.shared.global [%0],[%1],16;\n" :: "r"(d), "l"(s) : "memory");
}
__device__ __forceinline__ void cp_commit() {
    asm volatile("cp.async.commit_group;\n" ::: "memory");
}
template<int N> __device__ __forceinline__ void cp_wait() {
    asm volatile("cp.async.wait_group %0;\n" :: "n"(N) : "memory");
}
// fp16 mma: D(f32) += A(f16 4reg) * B(f16 2reg), m16n8k16 row.col
__device__ __forceinline__ void mma16(float* c, const unsigned* a, const unsigned* b) {
    asm volatile(
        "mma.sync.aligned.m16n8k16.row.col.f32.f16.f16.f32 "
        "{%0,%1,%2,%3},{%4,%5,%6,%7},{%8,%9},{%0,%1,%2,%3};\n"
        : "+f"(c[0]), "+f"(c[1]), "+f"(c[2]), "+f"(c[3])
        : "r"(a[0]), "r"(a[1]), "r"(a[2]), "r"(a[3]), "r"(b[0]), "r"(b[1]));
}
__device__ __forceinline__ void ldsm4(unsigned& r0, unsigned& r1, unsigned& r2, unsigned& r3,
                                      unsigned addr) {
    asm volatile("ldmatrix.sync.aligned.m8n8.x4.shared.b16 {%0,%1,%2,%3},[%4];\n"
                 : "=r"(r0), "=r"(r1), "=r"(r2), "=r"(r3) : "r"(addr));
}

// ---------------- mask dtype sniff + convert + bit-pack ----------------
__global__ void mask_convert(const unsigned int* __restrict__ w, int n) {
    __shared__ int not01, not0f;
    if (threadIdx.x == 0) { not01 = 0; not0f = 0; }
    __syncthreads();
    int b01 = 0, b0f = 0;
    for (int i = threadIdx.x; i < 2048; i += blockDim.x) {
        unsigned v = w[i];
        if (v > 1u) b01 = 1;
        if (v != 0u && v != 0x3F800000u) b0f = 1;
    }
    if (b01) atomicOr(&not01, 1);
    if (b0f) atomicOr(&not0f, 1);
    __syncthreads();
    int mode = (!not01) ? 1 : ((!not0f) ? 2 : 0); // 1=int32, 2=float32, 0=uint8
    int gid = blockIdx.x * blockDim.x + threadIdx.x;
    int stride = gridDim.x * blockDim.x;
    for (int wi = gid; wi < n / 32; wi += stride) {
        unsigned bits = 0;
        for (int k = 0; k < 32; k++) {
            int i = wi * 32 + k;
            int v;
            if (mode == 1)      v = (((const int*)w)[i] != 0);
            else if (mode == 2) v = (((const float*)w)[i] != 0.0f);
            else                v = (((const unsigned char*)w)[i] != 0);
            g_mask[i] = v;
            bits |= (v ? 1u : 0u) << k;
        }
        g_mbits[wi] = bits;
    }
}

// ---------------- pre-round inputs to fp16 (vectorized) ----------------
__global__ void prep_round(const float* __restrict__ X,
                           const float* __restrict__ Wq, const float* __restrict__ Wk,
                           const float* __restrict__ Wv, const float* __restrict__ Wo) {
    int gid = blockIdx.x * blockDim.x + threadIdx.x;
    int stride = gridDim.x * blockDim.x;
    for (int i = gid; i < NTOK * DMODEL / 4; i += stride) {
        float4 v = ((const float4*)X)[i];
        __half2 h0 = __floats2half2_rn(v.x, v.y);
        __half2 h1 = __floats2half2_rn(v.z, v.w);
        ((__half2*)g_x)[2 * i] = h0;
        ((__half2*)g_x)[2 * i + 1] = h1;
    }
    for (int i = gid; i < DMODEL * DMODEL / 4; i += stride) {
        float4 a = ((const float4*)Wq)[i];
        float4 b = ((const float4*)Wk)[i];
        float4 c = ((const float4*)Wv)[i];
        float4 d = ((const float4*)Wo)[i];
        ((__half2*)g_wq)[2 * i]     = __floats2half2_rn(a.x, a.y);
        ((__half2*)g_wq)[2 * i + 1] = __floats2half2_rn(a.z, a.w);
        ((__half2*)g_wk)[2 * i]     = __floats2half2_rn(b.x, b.y);
        ((__half2*)g_wk)[2 * i + 1] = __floats2half2_rn(b.z, b.w);
        ((__half2*)g_wv)[2 * i]     = __floats2half2_rn(c.x, c.y);
        ((__half2*)g_wv)[2 * i + 1] = __floats2half2_rn(c.z, c.w);
        ((__half2*)g_wo)[2 * i]     = __floats2half2_rn(d.x, d.y);
        ((__half2*)g_wo)[2 * i + 1] = __floats2half2_rn(d.z, d.w);
    }
}

// ---------------- GEMM: 128x128 CTA tile, 32x64 warp, 256 thr, fp16, k-slab 64 ----------------
#define GK 64
#define GLDH 72
#define A_H (128 * GLDH)
#define STG_H (256 * GLDH)                 // 18432 halves
#define GEMM_SMEM (3 * STG_H * 2)          // 110592 bytes -> 2 CTAs/SM

__global__ __launch_bounds__(256, 2) void qkv_gemm(
    const float* __restrict__ bq, const float* __restrict__ bk, const float* __restrict__ bv)
{
    extern __shared__ __half smh[];
    const int z = blockIdx.z;
    const __half* Wg   = (z == 0) ? g_wq : (z == 1) ? g_wk : g_wv;
    const float* bias  = (z == 0) ? bq : (z == 1) ? bk : bv;
    __half* out        = (z == 0) ? g_q : (z == 1) ? g_k : g_v;
    const float osc    = (z == 0) ? 0.125f : 1.0f;

    const int t = threadIdx.x, warp = t >> 5, lane = t & 31;
    const int q = lane & 3;
    const int wm = warp >> 1, wn = warp & 1;
    const int n0 = blockIdx.y << 7, e0 = blockIdx.x << 7;

    const int arow  = (lane & 7) + ((lane >> 3) & 1) * 8;
    const int acolB = (lane >> 4) << 4;
    const int brow  = ((lane >> 4) << 3) + (lane & 7);
    const int bcolB = ((lane >> 3) & 1) << 4;

    auto stage = [&](int slab) {
        const int kk = slab * GK;
        __half* base = smh + (slab % 3) * STG_H;
        const unsigned aB = smem_u32(base), bB = aB + A_H * 2;
#pragma unroll
        for (int j = 0; j < 4; j++) {
            int ck = t + (j << 8);
            int r = ck >> 3, c = ck & 7;
            cp16(aB + (unsigned)(r * 144 + c * 16),
                 g_x + (size_t)(n0 + r) * DMODEL + kk + c * 8);
        }
#pragma unroll
        for (int j = 0; j < 4; j++) {
            int ck = t + (j << 8);
            int r = ck >> 3, c = ck & 7;
            cp16(bB + (unsigned)(r * 144 + c * 16),
                 Wg + (size_t)(e0 + r) * DMODEL + kk + c * 8);
        }
        cp_commit();
    };

    stage(0); stage(1);
    float acc[2][8][4] = {};
    for (int it = 0; it < 8; it++) {
        if (it < 7) cp_wait<1>(); else cp_wait<0>();
        __syncthreads();
        if (it + 2 < 8) stage(it + 2); else cp_commit();
        __half* base = smh + (it % 3) * STG_H;
        const unsigned xa = smem_u32(base) + (unsigned)((wm * 32 + arow) * 144 + acolB);
        const unsigned wa = smem_u32(base) + (unsigned)(A_H * 2 + (wn * 64 + brow) * 144 + bcolB);
#pragma unroll
        for (int kc = 0; kc < 4; kc++) {
            unsigned af[2][4], bf[8][2];
#pragma unroll
            for (int mf = 0; mf < 2; mf++)
                ldsm4(af[mf][0], af[mf][1], af[mf][2], af[mf][3],
                      xa + (unsigned)(mf * 16 * 144 + kc * 32));
#pragma unroll
            for (int np = 0; np < 4; np++) {
                unsigned r0, r1, r2, r3;
                ldsm4(r0, r1, r2, r3, wa + (unsigned)(np * 16 * 144 + kc * 32));
                bf[2 * np][0] = r0;     bf[2 * np][1] = r1;
                bf[2 * np + 1][0] = r2; bf[2 * np + 1][1] = r3;
            }
#pragma unroll
            for (int mf = 0; mf < 2; mf++)
#pragma unroll
                for (int nf = 0; nf < 8; nf++) mma16(acc[mf][nf], af[mf], bf[nf]);
        }
        // no trailing barrier: next iteration's leading barrier orders buffer reuse
    }

    const int g = lane >> 2;
#pragma unroll
    for (int mf = 0; mf < 2; mf++) {
        int ntA = n0 + wm * 32 + mf * 16 + g;
        int ntB = ntA + 8;
#pragma unroll
        for (int nf = 0; nf < 8; nf++) {
            int e = e0 + wn * 64 + nf * 8 + 2 * q;
            int hh = e >> 6, dh = e & 63;
            float b0v = bias[e], b1v = bias[e + 1];
            __half2 hA = __floats2half2_rn((acc[mf][nf][0] + b0v) * osc,
                                           (acc[mf][nf][1] + b1v) * osc);
            __half2 hB = __floats2half2_rn((acc[mf][nf][2] + b0v) * osc,
                                           (acc[mf][nf][3] + b1v) * osc);
            int bA = ntA >> 11, mA = ntA & 2047;
            int bB_ = ntB >> 11, mB = ntB & 2047;
            if (z == 2) {
                size_t baseA = ((size_t)bA * 8 + hh) * DHEAD;
                size_t baseB = ((size_t)bB_ * 8 + hh) * DHEAD;
                out[(baseA + dh) * M + mA]     = __low2half(hA);
                out[(baseA + dh + 1) * M + mA] = __high2half(hA);
                out[(baseB + dh) * M + mB]     = __low2half(hB);
                out[(baseB + dh + 1) * M + mB] = __high2half(hB);
            } else {
                *(__half2*)&out[(((size_t)bA * 8 + hh) * M + mA) * DHEAD + dh] = hA;
                *(__half2*)&out[(((size_t)bB_ * 8 + hh) * M + mB) * DHEAD + dh] = hB;
            }
        }
    }
}

// ---------------- output projection + mask ----------------
__global__ __launch_bounds__(256, 2) void oproj_gemm(
    const float* __restrict__ bo, float* __restrict__ out)
{
    extern __shared__ __half smh[];
    const int t = threadIdx.x, warp = t >> 5, lane = t & 31;
    const int q = lane & 3;
    const int wm = warp >> 1, wn = warp & 1;
    const int n0 = blockIdx.y << 7, e0 = blockIdx.x << 7;

    const int arow  = (lane & 7) + ((lane >> 3) & 1) * 8;
    const int acolB = (lane >> 4) << 4;
    const int brow  = ((lane >> 4) << 3) + (lane & 7);
    const int bcolB = ((lane >> 3) & 1) << 4;

    auto stage = [&](int slab) {
        const int kk = slab * GK;
        __half* base = smh + (slab % 3) * STG_H;
        const unsigned aB = smem_u32(base), bB = aB + A_H * 2;
#pragma unroll
        for (int j = 0; j < 4; j++) {
            int ck = t + (j << 8);
            int r = ck >> 3, c = ck & 7;
            cp16(aB + (unsigned)(r * 144 + c * 16),
                 g_ao + (size_t)(n0 + r) * DMODEL + kk + c * 8);
        }
#pragma unroll
        for (int j = 0; j < 4; j++) {
            int ck = t + (j << 8);
            int r = ck >> 3, c = ck & 7;
            cp16(bB + (unsigned)(r * 144 + c * 16),
                 g_wo + (size_t)(e0 + r) * DMODEL + kk + c * 8);
        }
        cp_commit();
    };

    stage(0); stage(1);
    float acc[2][8][4] = {};
    for (int it = 0; it < 8; it++) {
        if (it < 7) cp_wait<1>(); else cp_wait<0>();
        __syncthreads();
        if (it + 2 < 8) stage(it + 2); else cp_commit();
        __half* base = smh + (it % 3) * STG_H;
        const unsigned xa = smem_u32(base) + (unsigned)((wm * 32 + arow) * 144 + acolB);
        const unsigned wa = smem_u32(base) + (unsigned)(A_H * 2 + (wn * 64 + brow) * 144 + bcolB);
#pragma unroll
        for (int kc = 0; kc < 4; kc++) {
            unsigned af[2][4], bf[8][2];
#pragma unroll
            for (int mf = 0; mf < 2; mf++)
                ldsm4(af[mf][0], af[mf][1], af[mf][2], af[mf][3],
                      xa + (unsigned)(mf * 16 * 144 + kc * 32));
#pragma unroll
            for (int np = 0; np < 4; np++) {
                unsigned r0, r1, r2, r3;
                ldsm4(r0, r1, r2, r3, wa + (unsigned)(np * 16 * 144 + kc * 32));
                bf[2 * np][0] = r0;     bf[2 * np][1] = r1;
                bf[2 * np + 1][0] = r2; bf[2 * np + 1][1] = r3;
            }
#pragma unroll
            for (int mf = 0; mf < 2; mf++)
#pragma unroll
                for (int nf = 0; nf < 8; nf++) mma16(acc[mf][nf], af[mf], bf[nf]);
        }
    }

    const int g = lane >> 2;
#pragma unroll
    for (int mf = 0; mf < 2; mf++) {
        int ntA = n0 + wm * 32 + mf * 16 + g;
        int ntB = ntA + 8;
        float mkA = (float)g_mask[ntA];
        float mkB = (float)g_mask[ntB];
#pragma unroll
        for (int nf = 0; nf < 8; nf++) {
            int e = e0 + wn * 64 + nf * 8 + 2 * q;
            float b0v = bo[e], b1v = bo[e + 1];
            float2 rA = make_float2((acc[mf][nf][0] + b0v) * mkA,
                                    (acc[mf][nf][1] + b1v) * mkA);
            float2 rB = make_float2((acc[mf][nf][2] + b0v) * mkB,
                                    (acc[mf][nf][3] + b1v) * mkB);
            *(float2*)&out[(size_t)ntA * DMODEL + e] = rA;
            *(float2*)&out[(size_t)ntB * DMODEL + e] = rB;
        }
    }
}

// ---------------- attention: banded fp16, P in registers, arithmetic bias ----------------
#define KLDH 72   // halves, 144 B rows
#define ATT_SMEM (18432 * 2 + 64 * 4)   // 37120

__global__ __launch_bounds__(256, 2) void attn_kernel() {
    extern __shared__ __half smh[];
    __half* Ks0    = smh;                          // [2][64][72]
    __half* Vt0    = smh + 2 * 64 * KLDH;          // [2][64][72], row=d, col=key
    unsigned* mbw  = (unsigned*)(smh + 4 * 64 * KLDH);

    const int t = threadIdx.x, warp = t >> 5, lane = t & 31;
    const int g = lane >> 2, q = lane & 3;
    const int bh = blockIdx.y, b = bh >> 3, hh = bh & 7;
    const int m0 = blockIdx.x << 7;
    const __half* qb = g_q + (size_t)bh * M * DHEAD;
    const __half* kb = g_k + (size_t)bh * M * DHEAD;
    const __half* vbT = g_v + (size_t)bh * DHEAD * M;

    if (t < 64) mbw[t] = g_mbits[b * 64 + t];

    const int mw = m0 + warp * 16;
    unsigned qf[4][4];
    {
        const __half* q0 = qb + (size_t)(mw + g) * DHEAD;
        const __half* q1 = qb + (size_t)(mw + g + 8) * DHEAD;
#pragma unroll
        for (int kc = 0; kc < 4; kc++) {
            qf[kc][0] = *(const unsigned*)&q0[kc * 16 + 2 * q];
            qf[kc][1] = *(const unsigned*)&q1[kc * 16 + 2 * q];
            qf[kc][2] = *(const unsigned*)&q0[kc * 16 + 8 + 2 * q];
            qf[kc][3] = *(const unsigned*)&q1[kc * 16 + 8 + 2 * q];
        }
    }

    float oacc[8][4] = {};
    float l0 = 0.0f, l1 = 0.0f;

    const int brow  = ((lane >> 4) << 3) + (lane & 7);
    const int bcolB = ((lane >> 3) & 1) << 4;
    const unsigned kfb = (unsigned)(brow * 144 + bcolB);
    const unsigned ks_base = smem_u32(Ks0);
    const unsigned vs_base = smem_u32(Vt0);

    auto stage = [&](int tile, int buf) {
        const __half* ksrc = kb + (size_t)(tile * 64) * DHEAD;
        const __half* vsrc = vbT + tile * 64;
        __half* kd = Ks0 + buf * 64 * KLDH;
        __half* vd = Vt0 + buf * 64 * KLDH;
#pragma unroll
        for (int j = 0; j < 2; j++) {
            int ck = t + j * 256;
            int row = ck >> 3, c = ck & 7;
            cp16(smem_u32(kd) + (unsigned)(row * 144 + c * 16), ksrc + row * 64 + c * 8);
            cp16(smem_u32(vd) + (unsigned)(row * 144 + c * 16), vsrc + (size_t)row * M + c * 8);
        }
    };

    const int tlo = max(0, (m0 >> 6) - 1);
    const int thi = min(M / 64 - 1, (m0 >> 6) + 2);

    stage(tlo, 0); cp_commit();

    for (int tile = tlo; tile <= thi; tile++) {
        const int bufi = (tile - tlo) & 1;
        if (tile < thi) { stage(tile + 1, bufi ^ 1); cp_commit(); cp_wait<1>(); }
        else cp_wait<0>();
        __syncthreads();

        const int n0 = tile << 6;
        if (n0 <= mw + 79 && n0 + 63 >= mw - 64) {
            const unsigned kbuf = ks_base + bufi * (64 * 144) + kfb;
            const unsigned vbuf = vs_base + bufi * (64 * 144) + kfb;

            // ---- S = Q K^T ----
            float sacc[8][4] = {};
#pragma unroll
            for (int kc = 0; kc < 4; kc++) {
                unsigned bb[8][2];
#pragma unroll
                for (int np = 0; np < 4; np++) {
                    unsigned r0, r1, r2, r3;
                    ldsm4(r0, r1, r2, r3, kbuf + (unsigned)(np * 16 * 144 + kc * 32));
                    bb[2 * np][0] = r0;     bb[2 * np][1] = r1;
                    bb[2 * np + 1][0] = r2; bb[2 * np + 1][1] = r3;
                }
#pragma unroll
                for (int nf = 0; nf < 8; nf++) mma16(sacc[nf], qf[kc], bb[nf]);
            }

            // ---- softmax (static max): P = mask ? exp(S - |m-n|) : 0 ----
            const unsigned w0 = mbw[tile * 2], w1 = mbw[tile * 2 + 1];
            const int mg0 = mw + g, mg1 = mg0 + 8;
            unsigned pA[8], pB[8];
#pragma unroll
            for (int nf = 0; nf < 8; nf++) {
                int off = nf * 8 + 2 * q;
                unsigned wsel = (nf < 4) ? w0 : w1;
                int sh = off & 31;
                bool v0m = (wsel >> sh) & 1;
                bool v1m = (wsel >> (sh + 1)) & 1;
                int n_ = n0 + off;
                float d00 = (float)abs(mg0 - n_), d01 = (float)abs(mg0 - n_ - 1);
                float d10 = (float)abs(mg1 - n_), d11 = (float)abs(mg1 - n_ - 1);
                float p0 = v0m ? __expf(sacc[nf][0] - d00) : 0.0f;
                float p1 = v1m ? __expf(sacc[nf][1] - d01) : 0.0f;
                float p2 = v0m ? __expf(sacc[nf][2] - d10) : 0.0f;
                float p3 = v1m ? __expf(sacc[nf][3] - d11) : 0.0f;
                __half2 h01 = __floats2half2_rn(p0, p1);
                __half2 h23 = __floats2half2_rn(p2, p3);
                l0 += __low2float(h01) + __high2float(h01);
                l1 += __low2float(h23) + __high2float(h23);
                pA[nf] = *(unsigned*)&h01;
                pB[nf] = *(unsigned*)&h23;
            }

            // ---- O += P V (P A-frags direct from registers) ----
#pragma unroll
            for (int kc = 0; kc < 4; kc++) {
                unsigned pa[4];
                pa[0] = pA[2 * kc];
                pa[1] = pB[2 * kc];
                pa[2] = pA[2 * kc + 1];
                pa[3] = pB[2 * kc + 1];
                unsigned vv[8][2];
#pragma unroll
                for (int dp = 0; dp < 4; dp++) {
                    unsigned r0, r1, r2, r3;
                    ldsm4(r0, r1, r2, r3, vbuf + (unsigned)(dp * 16 * 144 + kc * 32));
                    vv[2 * dp][0] = r0;     vv[2 * dp][1] = r1;
                    vv[2 * dp + 1][0] = r2; vv[2 * dp + 1][1] = r3;
                }
#pragma unroll
                for (int df = 0; df < 8; df++) mma16(oacc[df], pa, vv[df]);
            }
        }
        __syncthreads();
    }

    l0 += __shfl_xor_sync(0xffffffffu, l0, 1);
    l0 += __shfl_xor_sync(0xffffffffu, l0, 2);
    l1 += __shfl_xor_sync(0xffffffffu, l1, 1);
    l1 += __shfl_xor_sync(0xffffffffu, l1, 2);
    float i0 = 1.0f / fmaxf(l0, 1e-30f);
    float i1 = 1.0f / fmaxf(l1, 1e-30f);
    __half* ob = g_ao + (size_t)b * M * DMODEL + (size_t)hh * DHEAD;
#pragma unroll
    for (int df = 0; df < 8; df++) {
        *(__half2*)&ob[(size_t)(mw + g) * DMODEL + df * 8 + 2 * q] =
            __floats2half2_rn(oacc[df][0] * i0, oacc[df][1] * i0);
        *(__half2*)&ob[(size_t)(mw + g + 8) * DMODEL + df * 8 + 2 * q] =
            __floats2half2_rn(oacc[df][2] * i1, oacc[df][3] * i1);
    }
}

// ---------------- launch ----------------
extern "C" void kernel_launch(void* const* d_in, const int* in_sizes, int n_in,
                              void* d_out, int out_size) {
    const float* h  = (const float*)d_in[0];
    const void*  pm = d_in[1];
    const float* Wq = (const float*)d_in[2];
    const float* bq = (const float*)d_in[3];
    const float* Wk = (const float*)d_in[4];
    const float* bk = (const float*)d_in[5];
    const float* Wv = (const float*)d_in[6];
    const float* bv = (const float*)d_in[7];
    const float* Wo = (const float*)d_in[8];
    const float* bo = (const float*)d_in[9];
    float* out = (float*)d_out;

    mask_convert<<<32, 256>>>((const unsigned int*)pm, NTOK);
    prep_round<<<296, 256>>>(h, Wq, Wk, Wv, Wo);

    cudaFuncSetAttribute(qkv_gemm, cudaFuncAttributeMaxDynamicSharedMemorySize, GEMM_SMEM);
    cudaFuncSetAttribute(oproj_gemm, cudaFuncAttributeMaxDynamicSharedMemorySize, GEMM_SMEM);
    cudaFuncSetAttribute(attn_kernel, cudaFuncAttributeMaxDynamicSharedMemorySize, ATT_SMEM);

    dim3 g1(DMODEL / 128, NTOK / 128, 3);
    qkv_gemm<<<g1, 256, GEMM_SMEM>>>(bq, bk, bv);

    dim3 g2(M / 128, BH);
    attn_kernel<<<g2, 256, ATT_SMEM>>>();

    dim3 g3(DMODEL / 128, NTOK / 128);
    oproj_gemm<<<g3, 256, GEMM_SMEM>>>(bo, out);
}

// round 17
// speedup vs baseline: 1.1914x; 1.0791x over previous
#include <cuda_runtime.h>
#include <cuda_fp16.h>
#include <math.h>

#define B 4
#define M 2048
#define DMODEL 512
#define NHEAD 8
#define DHEAD 64
#define NTOK (B*M)          // 8192
#define BH (B*NHEAD)        // 32

// ---------------- scratch (device globals) ----------------
__device__ __half g_x[NTOK * DMODEL];     // h, fp16
__device__ __half g_wq[DMODEL * DMODEL];  // weights, fp16
__device__ __half g_wk[DMODEL * DMODEL];
__device__ __half g_wv[DMODEL * DMODEL];
__device__ __half g_wo[DMODEL * DMODEL];
__device__ __half g_q[BH * M * DHEAD];    // [b,h,m,dh], fp16, pre-scaled log2e/8
__device__ __half g_k[BH * M * DHEAD];    // [b,h,m,dh] fp16
__device__ __half g_v[BH * DHEAD * M];    // [b,h,dh,m] TRANSPOSED, fp16
__device__ __half g_ao[NTOK * DMODEL];    // attention output [b,m,d], fp16
__device__ int    g_mask[NTOK];
__device__ unsigned g_mbits[NTOK / 32];   // packed mask bits

// ---------------- ptx helpers ----------------
__device__ __forceinline__ unsigned smem_u32(const void* p) {
    return (unsigned)__cvta_generic_to_shared(p);
}
__device__ __forceinline__ void cp16(unsigned d, const void* s) {
    asm volatile("cp.async.cg.shared.global [%0],[%1],16;\n" :: "r"(d), "l"(s) : "memory");
}
__device__ __forceinline__ void cp_commit() {
    asm volatile("cp.async.commit_group;\n" ::: "memory");
}
template<int N> __device__ __forceinline__ void cp_wait() {
    asm volatile("cp.async.wait_group %0;\n" :: "n"(N) : "memory");
}
__device__ __forceinline__ void mma16(float* c, const unsigned* a, const unsigned* b) {
    asm volatile(
        "mma.sync.aligned.m16n8k16.row.col.f32.f16.f16.f32 "
        "{%0,%1,%2,%3},{%4,%5,%6,%7},{%8,%9},{%0,%1,%2,%3};\n"
        : "+f"(c[0]), "+f"(c[1]), "+f"(c[2]), "+f"(c[3])
        : "r"(a[0]), "r"(a[1]), "r"(a[2]), "r"(a[3]), "r"(b[0]), "r"(b[1]));
}
__device__ __forceinline__ void ldsm4(unsigned& r0, unsigned& r1, unsigned& r2, unsigned& r3,
                                      unsigned addr) {
    asm volatile("ldmatrix.sync.aligned.m8n8.x4.shared.b16 {%0,%1,%2,%3},[%4];\n"
                 : "=r"(r0), "=r"(r1), "=r"(r2), "=r"(r3) : "r"(addr));
}
__device__ __forceinline__ unsigned ex2h2(unsigned u) {
    unsigned r; asm("ex2.approx.f16x2 %0,%1;" : "=r"(r) : "r"(u)); return r;
}

// ---------------- prep: mask sniff/convert/pack + fp16 rounding of inputs ----------------
__global__ void prep_all(const float* __restrict__ X,
                         const float* __restrict__ Wq, const float* __restrict__ Wk,
                         const float* __restrict__ Wv, const float* __restrict__ Wo,
                         const unsigned int* __restrict__ w) {
    __shared__ int not01, not0f;
    if (threadIdx.x == 0) { not01 = 0; not0f = 0; }
    __syncthreads();
    int b01 = 0, b0f = 0;
    for (int i = threadIdx.x; i < 2048; i += blockDim.x) {
        unsigned v = w[i];
        if (v > 1u) b01 = 1;
        if (v != 0u && v != 0x3F800000u) b0f = 1;
    }
    if (b01) atomicOr(&not01, 1);
    if (b0f) atomicOr(&not0f, 1);
    __syncthreads();
    int mode = (!not01) ? 1 : ((!not0f) ? 2 : 0); // 1=int32, 2=float32, 0=uint8
    int gid = blockIdx.x * blockDim.x + threadIdx.x;
    int stride = gridDim.x * blockDim.x;
    for (int wi = gid; wi < NTOK / 32; wi += stride) {
        unsigned bits = 0;
        for (int k = 0; k < 32; k++) {
            int i = wi * 32 + k;
            int v;
            if (mode == 1)      v = (((const int*)w)[i] != 0);
            else if (mode == 2) v = (((const float*)w)[i] != 0.0f);
            else                v = (((const unsigned char*)w)[i] != 0);
            g_mask[i] = v;
            bits |= (v ? 1u : 0u) << k;
        }
        g_mbits[wi] = bits;
    }
    for (int i = gid; i < NTOK * DMODEL / 4; i += stride) {
        float4 v = ((const float4*)X)[i];
        ((__half2*)g_x)[2 * i]     = __floats2half2_rn(v.x, v.y);
        ((__half2*)g_x)[2 * i + 1] = __floats2half2_rn(v.z, v.w);
    }
    for (int i = gid; i < DMODEL * DMODEL / 4; i += stride) {
        float4 a = ((const float4*)Wq)[i];
        float4 b = ((const float4*)Wk)[i];
        float4 c = ((const float4*)Wv)[i];
        float4 d = ((const float4*)Wo)[i];
        ((__half2*)g_wq)[2 * i]     = __floats2half2_rn(a.x, a.y);
        ((__half2*)g_wq)[2 * i + 1] = __floats2half2_rn(a.z, a.w);
        ((__half2*)g_wk)[2 * i]     = __floats2half2_rn(b.x, b.y);
        ((__half2*)g_wk)[2 * i + 1] = __floats2half2_rn(b.z, b.w);
        ((__half2*)g_wv)[2 * i]     = __floats2half2_rn(c.x, c.y);
        ((__half2*)g_wv)[2 * i + 1] = __floats2half2_rn(c.z, c.w);
        ((__half2*)g_wo)[2 * i]     = __floats2half2_rn(d.x, d.y);
        ((__half2*)g_wo)[2 * i + 1] = __floats2half2_rn(d.z, d.w);
    }
}

// ---------------- GEMM: 128x128 CTA tile, 32x64 warp, 256 thr, fp16, k-slab 64 ----------------
#define GK 64
#define GLDH 72
#define A_H (128 * GLDH)
#define STG_H (256 * GLDH)                 // 18432 halves
#define GEMM_SMEM (3 * STG_H * 2)          // 110592 bytes -> 2 CTAs/SM

__global__ __launch_bounds__(256, 2) void qkv_gemm(
    const float* __restrict__ bq, const float* __restrict__ bk, const float* __restrict__ bv)
{
    extern __shared__ __half smh[];
    const int z = blockIdx.z;
    const __half* Wg   = (z == 0) ? g_wq : (z == 1) ? g_wk : g_wv;
    const float* bias  = (z == 0) ? bq : (z == 1) ? bk : bv;
    __half* out        = (z == 0) ? g_q : (z == 1) ? g_k : g_v;
    const float osc    = (z == 0) ? 0.125f * 1.44269504f : 1.0f;  // fold log2e into Q

    const int t = threadIdx.x, warp = t >> 5, lane = t & 31;
    const int q = lane & 3;
    const int wm = warp >> 1, wn = warp & 1;
    const int n0 = blockIdx.y << 7, e0 = blockIdx.x << 7;

    const int arow  = (lane & 7) + ((lane >> 3) & 1) * 8;
    const int acolB = (lane >> 4) << 4;
    const int brow  = ((lane >> 4) << 3) + (lane & 7);
    const int bcolB = ((lane >> 3) & 1) << 4;

    auto stage = [&](int slab) {
        const int kk = slab * GK;
        __half* base = smh + (slab % 3) * STG_H;
        const unsigned aB = smem_u32(base), bB = aB + A_H * 2;
#pragma unroll
        for (int j = 0; j < 4; j++) {
            int ck = t + (j << 8);
            int r = ck >> 3, c = ck & 7;
            cp16(aB + (unsigned)(r * 144 + c * 16),
                 g_x + (size_t)(n0 + r) * DMODEL + kk + c * 8);
        }
#pragma unroll
        for (int j = 0; j < 4; j++) {
            int ck = t + (j << 8);
            int r = ck >> 3, c = ck & 7;
            cp16(bB + (unsigned)(r * 144 + c * 16),
                 Wg + (size_t)(e0 + r) * DMODEL + kk + c * 8);
        }
        cp_commit();
    };

    stage(0); stage(1);
    float acc[2][8][4] = {};
    for (int it = 0; it < 8; it++) {
        if (it < 7) cp_wait<1>(); else cp_wait<0>();
        __syncthreads();
        if (it + 2 < 8) stage(it + 2); else cp_commit();
        __half* base = smh + (it % 3) * STG_H;
        const unsigned xa = smem_u32(base) + (unsigned)((wm * 32 + arow) * 144 + acolB);
        const unsigned wa = smem_u32(base) + (unsigned)(A_H * 2 + (wn * 64 + brow) * 144 + bcolB);
#pragma unroll
        for (int kc = 0; kc < 4; kc++) {
            unsigned af[2][4], bf[8][2];
#pragma unroll
            for (int mf = 0; mf < 2; mf++)
                ldsm4(af[mf][0], af[mf][1], af[mf][2], af[mf][3],
                      xa + (unsigned)(mf * 16 * 144 + kc * 32));
#pragma unroll
            for (int np = 0; np < 4; np++) {
                unsigned r0, r1, r2, r3;
                ldsm4(r0, r1, r2, r3, wa + (unsigned)(np * 16 * 144 + kc * 32));
                bf[2 * np][0] = r0;     bf[2 * np][1] = r1;
                bf[2 * np + 1][0] = r2; bf[2 * np + 1][1] = r3;
            }
#pragma unroll
            for (int mf = 0; mf < 2; mf++)
#pragma unroll
                for (int nf = 0; nf < 8; nf++) mma16(acc[mf][nf], af[mf], bf[nf]);
        }
    }

    const int g = lane >> 2;
#pragma unroll
    for (int mf = 0; mf < 2; mf++) {
        int ntA = n0 + wm * 32 + mf * 16 + g;
        int ntB = ntA + 8;
#pragma unroll
        for (int nf = 0; nf < 8; nf++) {
            int e = e0 + wn * 64 + nf * 8 + 2 * q;
            int hh = e >> 6, dh = e & 63;
            float b0v = bias[e], b1v = bias[e + 1];
            __half2 hA = __floats2half2_rn((acc[mf][nf][0] + b0v) * osc,
                                           (acc[mf][nf][1] + b1v) * osc);
            __half2 hB = __floats2half2_rn((acc[mf][nf][2] + b0v) * osc,
                                           (acc[mf][nf][3] + b1v) * osc);
            int bA = ntA >> 11, mA = ntA & 2047;
            int bB_ = ntB >> 11, mB = ntB & 2047;
            if (z == 2) {
                size_t baseA = ((size_t)bA * 8 + hh) * DHEAD;
                size_t baseB = ((size_t)bB_ * 8 + hh) * DHEAD;
                out[(baseA + dh) * M + mA]     = __low2half(hA);
                out[(baseA + dh + 1) * M + mA] = __high2half(hA);
                out[(baseB + dh) * M + mB]     = __low2half(hB);
                out[(baseB + dh + 1) * M + mB] = __high2half(hB);
            } else {
                *(__half2*)&out[(((size_t)bA * 8 + hh) * M + mA) * DHEAD + dh] = hA;
                *(__half2*)&out[(((size_t)bB_ * 8 + hh) * M + mB) * DHEAD + dh] = hB;
            }
        }
    }
}

// ---------------- output projection + mask ----------------
__global__ __launch_bounds__(256, 2) void oproj_gemm(
    const float* __restrict__ bo, float* __restrict__ out)
{
    extern __shared__ __half smh[];
    const int t = threadIdx.x, warp = t >> 5, lane = t & 31;
    const int q = lane & 3;
    const int wm = warp >> 1, wn = warp & 1;
    const int n0 = blockIdx.y << 7, e0 = blockIdx.x << 7;

    const int arow  = (lane & 7) + ((lane >> 3) & 1) * 8;
    const int acolB = (lane >> 4) << 4;
    const int brow  = ((lane >> 4) << 3) + (lane & 7);
    const int bcolB = ((lane >> 3) & 1) << 4;

    auto stage = [&](int slab) {
        const int kk = slab * GK;
        __half* base = smh + (slab % 3) * STG_H;
        const unsigned aB = smem_u32(base), bB = aB + A_H * 2;
#pragma unroll
        for (int j = 0; j < 4; j++) {
            int ck = t + (j << 8);
            int r = ck >> 3, c = ck & 7;
            cp16(aB + (unsigned)(r * 144 + c * 16),
                 g_ao + (size_t)(n0 + r) * DMODEL + kk + c * 8);
        }
#pragma unroll
        for (int j = 0; j < 4; j++) {
            int ck = t + (j << 8);
            int r = ck >> 3, c = ck & 7;
            cp16(bB + (unsigned)(r * 144 + c * 16),
                 g_wo + (size_t)(e0 + r) * DMODEL + kk + c * 8);
        }
        cp_commit();
    };

    stage(0); stage(1);
    float acc[2][8][4] = {};
    for (int it = 0; it < 8; it++) {
        if (it < 7) cp_wait<1>(); else cp_wait<0>();
        __syncthreads();
        if (it + 2 < 8) stage(it + 2); else cp_commit();
        __half* base = smh + (it % 3) * STG_H;
        const unsigned xa = smem_u32(base) + (unsigned)((wm * 32 + arow) * 144 + acolB);
        const unsigned wa = smem_u32(base) + (unsigned)(A_H * 2 + (wn * 64 + brow) * 144 + bcolB);
#pragma unroll
        for (int kc = 0; kc < 4; kc++) {
            unsigned af[2][4], bf[8][2];
#pragma unroll
            for (int mf = 0; mf < 2; mf++)
                ldsm4(af[mf][0], af[mf][1], af[mf][2], af[mf][3],
                      xa + (unsigned)(mf * 16 * 144 + kc * 32));
#pragma unroll
            for (int np = 0; np < 4; np++) {
                unsigned r0, r1, r2, r3;
                ldsm4(r0, r1, r2, r3, wa + (unsigned)(np * 16 * 144 + kc * 32));
                bf[2 * np][0] = r0;     bf[2 * np][1] = r1;
                bf[2 * np + 1][0] = r2; bf[2 * np + 1][1] = r3;
            }
#pragma unroll
            for (int mf = 0; mf < 2; mf++)
#pragma unroll
                for (int nf = 0; nf < 8; nf++) mma16(acc[mf][nf], af[mf], bf[nf]);
        }
    }

    const int g = lane >> 2;
#pragma unroll
    for (int mf = 0; mf < 2; mf++) {
        int ntA = n0 + wm * 32 + mf * 16 + g;
        int ntB = ntA + 8;
        float mkA = (float)g_mask[ntA];
        float mkB = (float)g_mask[ntB];
#pragma unroll
        for (int nf = 0; nf < 8; nf++) {
            int e = e0 + wn * 64 + nf * 8 + 2 * q;
            float b0v = bo[e], b1v = bo[e + 1];
            float2 rA = make_float2((acc[mf][nf][0] + b0v) * mkA,
                                    (acc[mf][nf][1] + b1v) * mkA);
            float2 rB = make_float2((acc[mf][nf][2] + b0v) * mkB,
                                    (acc[mf][nf][3] + b1v) * mkB);
            *(float2*)&out[(size_t)ntA * DMODEL + e] = rA;
            *(float2*)&out[(size_t)ntB * DMODEL + e] = rB;
        }
    }
}

// ---------------- attention: banded fp16, P in registers, ex2.f16x2 softmax ----------------
#define KLDH 72   // halves, 144 B rows
#define ATT_SMEM (18432 * 2 + 64 * 4)   // 37120

__global__ __launch_bounds__(256, 2) void attn_kernel() {
    extern __shared__ __half smh[];
    __half* Ks0    = smh;                          // [2][64][72]
    __half* Vt0    = smh + 2 * 64 * KLDH;          // [2][64][72], row=d, col=key
    unsigned* mbw  = (unsigned*)(smh + 4 * 64 * KLDH);

    const int t = threadIdx.x, warp = t >> 5, lane = t & 31;
    const int g = lane >> 2, q = lane & 3;
    const int bh = blockIdx.y, b = bh >> 3, hh = bh & 7;
    const int m0 = blockIdx.x << 7;
    const __half* qb = g_q + (size_t)bh * M * DHEAD;
    const __half* kb = g_k + (size_t)bh * M * DHEAD;
    const __half* vbT = g_v + (size_t)bh * DHEAD * M;
    const float L = 1.44269504f;

    if (t < 64) mbw[t] = g_mbits[b * 64 + t];

    const int mw = m0 + warp * 16;
    unsigned qf[4][4];
    {
        const __half* q0 = qb + (size_t)(mw + g) * DHEAD;
        const __half* q1 = qb + (size_t)(mw + g + 8) * DHEAD;
#pragma unroll
        for (int kc = 0; kc < 4; kc++) {
            qf[kc][0] = *(const unsigned*)&q0[kc * 16 + 2 * q];
            qf[kc][1] = *(const unsigned*)&q1[kc * 16 + 2 * q];
            qf[kc][2] = *(const unsigned*)&q0[kc * 16 + 8 + 2 * q];
            qf[kc][3] = *(const unsigned*)&q1[kc * 16 + 8 + 2 * q];
        }
    }

    float oacc[8][4] = {};
    float l0 = 0.0f, l1 = 0.0f;

    const int brow  = ((lane >> 4) << 3) + (lane & 7);
    const int bcolB = ((lane >> 3) & 1) << 4;
    const unsigned kfb = (unsigned)(brow * 144 + bcolB);
    const unsigned ks_base = smem_u32(Ks0);
    const unsigned vs_base = smem_u32(Vt0);

    auto stage = [&](int tile, int buf) {
        const __half* ksrc = kb + (size_t)(tile * 64) * DHEAD;
        const __half* vsrc = vbT + tile * 64;
        __half* kd = Ks0 + buf * 64 * KLDH;
        __half* vd = Vt0 + buf * 64 * KLDH;
#pragma unroll
        for (int j = 0; j < 2; j++) {
            int ck = t + j * 256;
            int row = ck >> 3, c = ck & 7;
            cp16(smem_u32(kd) + (unsigned)(row * 144 + c * 16), ksrc + row * 64 + c * 8);
            cp16(smem_u32(vd) + (unsigned)(row * 144 + c * 16), vsrc + (size_t)row * M + c * 8);
        }
    };

    const int tlo = max(0, (m0 >> 6) - 1);
    const int thi = min(M / 64 - 1, (m0 >> 6) + 2);

    stage(tlo, 0); cp_commit();

    for (int tile = tlo; tile <= thi; tile++) {
        const int bufi = (tile - tlo) & 1;
        if (tile < thi) { stage(tile + 1, bufi ^ 1); cp_commit(); cp_wait<1>(); }
        else cp_wait<0>();
        __syncthreads();

        const int n0 = tile << 6;
        // band +-32 per warp: keys needed are [mw-32, mw+47]
        if (n0 <= mw + 47 && n0 + 63 >= mw - 32) {
            const unsigned kbuf = ks_base + bufi * (64 * 144) + kfb;
            const unsigned vbuf = vs_base + bufi * (64 * 144) + kfb;

            // ---- S' = (QK^T)*log2e/8 (scale folded into Q) ----
            float sacc[8][4] = {};
#pragma unroll
            for (int kc = 0; kc < 4; kc++) {
                unsigned bb[8][2];
#pragma unroll
                for (int np = 0; np < 4; np++) {
                    unsigned r0, r1, r2, r3;
                    ldsm4(r0, r1, r2, r3, kbuf + (unsigned)(np * 16 * 144 + kc * 32));
                    bb[2 * np][0] = r0;     bb[2 * np][1] = r1;
                    bb[2 * np + 1][0] = r2; bb[2 * np + 1][1] = r3;
                }
#pragma unroll
                for (int nf = 0; nf < 8; nf++) mma16(sacc[nf], qf[kc], bb[nf]);
            }

            // ---- softmax: P = mask ? 2^(S' - |m-n|*log2e) : 0, via ex2.f16x2 ----
            const unsigned w0 = mbw[tile * 2], w1 = mbw[tile * 2 + 1];
            const int mg0 = mw + g, mg1 = mg0 + 8;
            unsigned pA[8], pB[8];
#pragma unroll
            for (int nf = 0; nf < 8; nf++) {
                int off = nf * 8 + 2 * q;
                unsigned wsel = (nf < 4) ? w0 : w1;
                int sh = off & 31;
                bool v0m = (wsel >> sh) & 1;
                bool v1m = (wsel >> (sh + 1)) & 1;
                int n_ = n0 + off;
                float d00 = (float)abs(mg0 - n_), d01 = (float)abs(mg0 - n_ - 1);
                float d10 = (float)abs(mg1 - n_), d11 = (float)abs(mg1 - n_ - 1);
                float t0 = v0m ? fmaf(d00, -L, sacc[nf][0]) : -64.0f;
                float t1 = v1m ? fmaf(d01, -L, sacc[nf][1]) : -64.0f;
                float t2 = v0m ? fmaf(d10, -L, sacc[nf][2]) : -64.0f;
                float t3 = v1m ? fmaf(d11, -L, sacc[nf][3]) : -64.0f;
                __half2 x01 = __floats2half2_rn(t0, t1);
                __half2 x23 = __floats2half2_rn(t2, t3);
                unsigned u01 = ex2h2(*(unsigned*)&x01);
                unsigned u23 = ex2h2(*(unsigned*)&x23);
                float2 f01 = __half22float2(*(__half2*)&u01);
                float2 f23 = __half22float2(*(__half2*)&u23);
                l0 += f01.x + f01.y;
                l1 += f23.x + f23.y;
                pA[nf] = u01;
                pB[nf] = u23;
            }

            // ---- O += P V ----
#pragma unroll
            for (int kc = 0; kc < 4; kc++) {
                unsigned pa[4];
                pa[0] = pA[2 * kc];
                pa[1] = pB[2 * kc];
                pa[2] = pA[2 * kc + 1];
                pa[3] = pB[2 * kc + 1];
                unsigned vv[8][2];
#pragma unroll
                for (int dp = 0; dp < 4; dp++) {
                    unsigned r0, r1, r2, r3;
                    ldsm4(r0, r1, r2, r3, vbuf + (unsigned)(dp * 16 * 144 + kc * 32));
                    vv[2 * dp][0] = r0;     vv[2 * dp][1] = r1;
                    vv[2 * dp + 1][0] = r2; vv[2 * dp + 1][1] = r3;
                }
#pragma unroll
                for (int df = 0; df < 8; df++) mma16(oacc[df], pa, vv[df]);
            }
        }
        __syncthreads();
    }

    l0 += __shfl_xor_sync(0xffffffffu, l0, 1);
    l0 += __shfl_xor_sync(0xffffffffu, l0, 2);
    l1 += __shfl_xor_sync(0xffffffffu, l1, 1);
    l1 += __shfl_xor_sync(0xffffffffu, l1, 2);
    float i0 = 1.0f / fmaxf(l0, 1e-30f);
    float i1 = 1.0f / fmaxf(l1, 1e-30f);
    __half* ob = g_ao + (size_t)b * M * DMODEL + (size_t)hh * DHEAD;
#pragma unroll
    for (int df = 0; df < 8; df++) {
        *(__half2*)&ob[(size_t)(mw + g) * DMODEL + df * 8 + 2 * q] =
            __floats2half2_rn(oacc[df][0] * i0, oacc[df][1] * i0);
        *(__half2*)&ob[(size_t)(mw + g + 8) * DMODEL + df * 8 + 2 * q] =
            __floats2half2_rn(oacc[df][2] * i1, oacc[df][3] * i1);
    }
}

// ---------------- launch ----------------
extern "C" void kernel_launch(void* const* d_in, const int* in_sizes, int n_in,
                              void* d_out, int out_size) {
    const float* h  = (const float*)d_in[0];
    const void*  pm = d_in[1];
    const float* Wq = (const float*)d_in[2];
    const float* bq = (const float*)d_in[3];
    const float* Wk = (const float*)d_in[4];
    const float* bk = (const float*)d_in[5];
    const float* Wv = (const float*)d_in[6];
    const float* bv = (const float*)d_in[7];
    const float* Wo = (const float*)d_in[8];
    const float* bo = (const float*)d_in[9];
    float* out = (float*)d_out;

    prep_all<<<296, 256>>>(h, Wq, Wk, Wv, Wo, (const unsigned int*)pm);

    cudaFuncSetAttribute(qkv_gemm, cudaFuncAttributeMaxDynamicSharedMemorySize, GEMM_SMEM);
    cudaFuncSetAttribute(oproj_gemm, cudaFuncAttributeMaxDynamicSharedMemorySize, GEMM_SMEM);
    cudaFuncSetAttribute(attn_kernel, cudaFuncAttributeMaxDynamicSharedMemorySize, ATT_SMEM);

    dim3 g1(DMODEL / 128, NTOK / 128, 3);
    qkv_gemm<<<g1, 256, GEMM_SMEM>>>(bq, bk, bv);

    dim3 g2(M / 128, BH);
    attn_kernel<<<g2, 256, ATT_SMEM>>>();

    dim3 g3(DMODEL / 128, NTOK / 128);
    oproj_gemm<<<g3, 256, GEMM_SMEM>>>(bo, out);
}